// round 5
// baseline (speedup 1.0000x reference)
#include <cuda_runtime.h>

#define D 128
#define NG 1024
#define MAXN 100000
#define BN_EPS 1e-5f

// ---------------- scratch (static device memory; no allocations allowed) ----
__device__ float g_agg[MAXN * D];
__device__ float g_h1[MAXN * D];
__device__ float g_xa[MAXN * D];
__device__ float g_xb[MAXN * D];
__device__ float g_W1p[3 * D * D];
__device__ float g_b1p[3 * D];
__device__ float g_pool[NG * D];
__device__ float g_hid[NG * D];

// ---------------- f32x2 helpers --------------------------------------------
__device__ __forceinline__ unsigned long long ffma2(unsigned long long a,
                                                    unsigned long long b,
                                                    unsigned long long c) {
    unsigned long long d;
    asm("fma.rn.f32x2 %0, %1, %2, %3;" : "=l"(d) : "l"(a), "l"(b), "l"(c));
    return d;
}
__device__ __forceinline__ unsigned long long pack_dup(float a) {
    unsigned long long r;
    asm("mov.b64 %0, {%1, %1};" : "=l"(r) : "f"(a));
    return r;
}
__device__ __forceinline__ unsigned long long pack2f(float lo, float hi) {
    unsigned long long r;
    asm("mov.b64 %0, {%1, %2};" : "=l"(r) : "f"(lo), "f"(hi));
    return r;
}
__device__ __forceinline__ float2 unpack2(unsigned long long v) {
    float2 r;
    asm("mov.b64 {%0, %1}, %2;" : "=f"(r.x), "=f"(r.y) : "l"(v));
    return r;
}

// ---------------- fold BN into W1/b1 ----------------------------------------
// y = (A@W1 + b1 - mean) * rsqrt(var+eps) * gamma + beta
//   = A@(W1*s) + (b1-mean)*s + beta,  s_c = rsqrt(var_c+eps)*gamma_c
__global__ void fold_bn_kernel(const float* __restrict__ W1,
                               const float* __restrict__ b1,
                               const float* __restrict__ gamma,
                               const float* __restrict__ beta,
                               const float* __restrict__ mean,
                               const float* __restrict__ var) {
    int k = blockIdx.x;      // 0..127
    int l = blockIdx.y;      // 0..2
    int c = threadIdx.x;     // 0..127
    float s = rsqrtf(var[l * D + c] + BN_EPS) * gamma[l * D + c];
    g_W1p[(l * D + k) * D + c] = W1[(l * D + k) * D + c] * s;
    if (k == 0)
        g_b1p[l * D + c] = (b1[l * D + c] - mean[l * D + c]) * s + beta[l * D + c];
}

// ---------------- simple vector copy (agg = x) ------------------------------
__global__ void copy_kernel(const float4* __restrict__ src, float4* __restrict__ dst, int n4) {
    int i = blockIdx.x * blockDim.x + threadIdx.x;
    if (i < n4) dst[i] = src[i];
}

__global__ void zero_kernel(float4* __restrict__ p, int n4) {
    int i = blockIdx.x * blockDim.x + threadIdx.x;
    if (i < n4) p[i] = make_float4(0.f, 0.f, 0.f, 0.f);
}

// ---------------- edge scatter: agg[dst] += x[src] --------------------------
// one warp per edge, one red.global.add.v4.f32 per lane (16B each, 512B/row)
// NOTE: edge_index is int32 (JAX x64 disabled downgrades int64 -> int32).
__global__ void scatter_edges(const float* __restrict__ x,
                              const int* __restrict__ ei,
                              float* __restrict__ agg, int nE) {
    int e = blockIdx.x * 8 + (threadIdx.x >> 5);
    if (e >= nE) return;
    int lane = threadIdx.x & 31;
    int s = __ldg(ei + e);
    int d = __ldg(ei + nE + e);
    float4 v = __ldg((const float4*)x + (long long)s * 32 + lane);
    const float4* dp = (const float4*)agg + (long long)d * 32 + lane;
    asm volatile("red.global.add.v4.f32 [%0], {%1, %2, %3, %4};"
                 :: "l"(dp), "f"(v.x), "f"(v.y), "f"(v.z), "f"(v.w)
                 : "memory");
}

// ---------------- pooling: g[batch[i]] += x[i] ------------------------------
__global__ void pool_nodes(const float* __restrict__ x,
                           const int* __restrict__ batch,
                           float* __restrict__ g, int n) {
    int i = blockIdx.x * 8 + (threadIdx.x >> 5);
    if (i >= n) return;
    int lane = threadIdx.x & 31;
    int b = __ldg(batch + i);
    float4 v = __ldg((const float4*)x + (long long)i * 32 + lane);
    const float4* dp = (const float4*)g + (long long)b * 32 + lane;
    asm volatile("red.global.add.v4.f32 [%0], {%1, %2, %3, %4};"
                 :: "l"(dp), "f"(v.x), "f"(v.y), "f"(v.z), "f"(v.w)
                 : "memory");
}

// ---------------- GEMM: C[n,128] = act(A[n,128] @ W[128,128] + bias) --------
// BM=128 rows/block, 256 threads, per-thread 8 rows x 8 cols (f32x2 packed).
// A staged transposed (float4-granular) in smem; W chunk (32x128) in smem.
__global__ __launch_bounds__(256, 2) void gemm_kernel(
    const float* __restrict__ A, const float* __restrict__ W,
    const float* __restrict__ bias, float* __restrict__ C, int n, int relu) {
    __shared__ float4 As4[8][130];   // [k4][row], pad 2 -> <=2-way store conflicts
    __shared__ float4 Ws4[32][32];   // [k][c4]

    int t = threadIdx.x;
    int tx = t & 15;                 // col group: cols 4*tx..+3 and 64+4*tx..+3
    int ty = t >> 4;                 // row group: rows 8*ty..+7
    int row0 = blockIdx.x * 128;

    unsigned long long acc[8][4];
#pragma unroll
    for (int i = 0; i < 8; i++)
#pragma unroll
        for (int j = 0; j < 4; j++) acc[i][j] = 0ull;

    for (int ko = 0; ko < 4; ko++) {
        // stage A tile (128 rows x 32 k) transposed
#pragma unroll
        for (int it = 0; it < 4; it++) {
            int idx = it * 256 + t;
            int k4 = idx & 7;
            int row = idx >> 3;
            int gr = row0 + row;
            float4 v = make_float4(0.f, 0.f, 0.f, 0.f);
            if (gr < n) v = __ldg((const float4*)A + (long long)gr * 32 + ko * 8 + k4);
            As4[k4][row] = v;
        }
        // stage W chunk (32 k x 128 c)
#pragma unroll
        for (int it = 0; it < 4; it++) {
            int idx = it * 256 + t;
            int kr = idx >> 5;
            int c4 = idx & 31;
            Ws4[kr][c4] = __ldg((const float4*)W + (long long)(ko * 32 + kr) * 32 + c4);
        }
        __syncthreads();

#pragma unroll
        for (int k4 = 0; k4 < 8; k4++) {
            unsigned long long w2[4][4];  // [kk][j]
#pragma unroll
            for (int kk = 0; kk < 4; kk++) {
                float4 wlo = Ws4[k4 * 4 + kk][tx];
                float4 whi = Ws4[k4 * 4 + kk][16 + tx];
                w2[kk][0] = pack2f(wlo.x, wlo.y);
                w2[kk][1] = pack2f(wlo.z, wlo.w);
                w2[kk][2] = pack2f(whi.x, whi.y);
                w2[kk][3] = pack2f(whi.z, whi.w);
            }
#pragma unroll
            for (int i = 0; i < 8; i++) {
                float4 a4 = As4[k4][ty * 8 + i];
#pragma unroll
                for (int kk = 0; kk < 4; kk++) {
                    float av = (kk == 0) ? a4.x : (kk == 1) ? a4.y : (kk == 2) ? a4.z : a4.w;
                    unsigned long long aa = pack_dup(av);
                    acc[i][0] = ffma2(aa, w2[kk][0], acc[i][0]);
                    acc[i][1] = ffma2(aa, w2[kk][1], acc[i][1]);
                    acc[i][2] = ffma2(aa, w2[kk][2], acc[i][2]);
                    acc[i][3] = ffma2(aa, w2[kk][3], acc[i][3]);
                }
            }
        }
        __syncthreads();
    }

    // epilogue
    float4 blo = __ldg((const float4*)bias + tx);
    float4 bhi = __ldg((const float4*)bias + 16 + tx);
#pragma unroll
    for (int i = 0; i < 8; i++) {
        int gr = row0 + ty * 8 + i;
        if (gr >= n) continue;
        float2 c0 = unpack2(acc[i][0]);
        float2 c1 = unpack2(acc[i][1]);
        float2 c2 = unpack2(acc[i][2]);
        float2 c3 = unpack2(acc[i][3]);
        float4 olo = make_float4(c0.x + blo.x, c0.y + blo.y, c1.x + blo.z, c1.y + blo.w);
        float4 ohi = make_float4(c2.x + bhi.x, c2.y + bhi.y, c3.x + bhi.z, c3.y + bhi.w);
        if (relu) {
            olo.x = fmaxf(olo.x, 0.f); olo.y = fmaxf(olo.y, 0.f);
            olo.z = fmaxf(olo.z, 0.f); olo.w = fmaxf(olo.w, 0.f);
            ohi.x = fmaxf(ohi.x, 0.f); ohi.y = fmaxf(ohi.y, 0.f);
            ohi.z = fmaxf(ohi.z, 0.f); ohi.w = fmaxf(ohi.w, 0.f);
        }
        ((float4*)C)[(long long)gr * 32 + tx] = olo;
        ((float4*)C)[(long long)gr * 32 + 16 + tx] = ohi;
    }
}

// ---------------- launch -----------------------------------------------------
extern "C" void kernel_launch(void* const* d_in, const int* in_sizes, int n_in,
                              void* d_out, int out_size) {
    const float* x        = (const float*)d_in[0];
    const int*   ei       = (const int*)d_in[1];      // int32 (JAX x64 disabled)
    const int*   batch    = (const int*)d_in[2];      // int32
    const float* W1       = (const float*)d_in[3];
    const float* b1       = (const float*)d_in[4];
    const float* gamma    = (const float*)d_in[5];
    const float* beta     = (const float*)d_in[6];
    const float* mean     = (const float*)d_in[7];
    const float* var      = (const float*)d_in[8];
    const float* W2       = (const float*)d_in[9];
    const float* b2       = (const float*)d_in[10];
    const float* hW1      = (const float*)d_in[11];
    const float* hb1      = (const float*)d_in[12];
    const float* hW2      = (const float*)d_in[13];
    const float* hb2      = (const float*)d_in[14];

    int n  = in_sizes[0] / D;
    int nE = in_sizes[1] / 2;

    float *agg, *h1, *xa, *xb, *W1p, *b1p, *pool, *hid;
    cudaGetSymbolAddress((void**)&agg,  g_agg);
    cudaGetSymbolAddress((void**)&h1,   g_h1);
    cudaGetSymbolAddress((void**)&xa,   g_xa);
    cudaGetSymbolAddress((void**)&xb,   g_xb);
    cudaGetSymbolAddress((void**)&W1p,  g_W1p);
    cudaGetSymbolAddress((void**)&b1p,  g_b1p);
    cudaGetSymbolAddress((void**)&pool, g_pool);
    cudaGetSymbolAddress((void**)&hid,  g_hid);

    int n4 = n * 32;                      // float4 count of a node matrix
    int copyGrid = (n4 + 255) / 256;
    int gemmGrid = (n + 127) / 128;
    int edgeGrid = (nE + 7) / 8;

    fold_bn_kernel<<<dim3(D, 3), D>>>(W1, b1, gamma, beta, mean, var);

    const float* xin = x;
    float* outs[3] = {xa, xb, xa};
    for (int l = 0; l < 3; l++) {
        copy_kernel<<<copyGrid, 256>>>((const float4*)xin, (float4*)agg, n4);
        scatter_edges<<<edgeGrid, 256>>>(xin, ei, agg, nE);
        gemm_kernel<<<gemmGrid, 256>>>(agg, W1p + l * D * D, b1p + l * D, h1, n, 1);
        gemm_kernel<<<gemmGrid, 256>>>(h1, W2 + (long long)l * D * D, b2 + l * D, outs[l], n, 1);
        xin = outs[l];
    }

    zero_kernel<<<(NG * 32 + 255) / 256, 256>>>((float4*)pool, NG * 32);
    pool_nodes<<<(n + 7) / 8, 256>>>(xin, batch, pool, n);
    gemm_kernel<<<(NG + 127) / 128, 256>>>(pool, hW1, hb1, hid, NG, 1);
    gemm_kernel<<<(NG + 127) / 128, 256>>>(hid, hW2, hb2, (float*)d_out, NG, 0);
}

// round 6
// speedup vs baseline: 1.3604x; 1.3604x over previous
#include <cuda_runtime.h>

#define D 128
#define NG 1024
#define MAXN 100000
#define MAXE 1600000
#define BN_EPS 1e-5f

// ---------------- scratch (static device memory) ----------------------------
__device__ float g_agg[MAXN * D];
__device__ float g_h1[MAXN * D];
__device__ float g_xa[MAXN * D];
__device__ float g_xb[MAXN * D];
__device__ float g_W1p[3 * D * D];
__device__ float g_b1p[3 * D];
__device__ float g_pool[NG * D];
__device__ float g_hid[NG * D];
// CSR
__device__ int g_deg[MAXN];
__device__ int g_off[MAXN + 1];
__device__ int g_cur[MAXN];
__device__ int g_col[MAXE];
__device__ int g_bsums[256];

// ---------------- f32x2 helpers --------------------------------------------
__device__ __forceinline__ unsigned long long ffma2(unsigned long long a,
                                                    unsigned long long b,
                                                    unsigned long long c) {
    unsigned long long d;
    asm("fma.rn.f32x2 %0, %1, %2, %3;" : "=l"(d) : "l"(a), "l"(b), "l"(c));
    return d;
}
__device__ __forceinline__ unsigned long long pack_dup(float a) {
    unsigned long long r;
    asm("mov.b64 %0, {%1, %1};" : "=l"(r) : "f"(a));
    return r;
}
__device__ __forceinline__ unsigned long long pack2f(float lo, float hi) {
    unsigned long long r;
    asm("mov.b64 %0, {%1, %2};" : "=l"(r) : "f"(lo), "f"(hi));
    return r;
}
__device__ __forceinline__ float2 unpack2(unsigned long long v) {
    float2 r;
    asm("mov.b64 {%0, %1}, %2;" : "=f"(r.x), "=f"(r.y) : "l"(v));
    return r;
}

// ---------------- fold BN into W1/b1 ----------------------------------------
__global__ void fold_bn_kernel(const float* __restrict__ W1,
                               const float* __restrict__ b1,
                               const float* __restrict__ gamma,
                               const float* __restrict__ beta,
                               const float* __restrict__ mean,
                               const float* __restrict__ var) {
    int k = blockIdx.x;
    int l = blockIdx.y;
    int c = threadIdx.x;
    float s = rsqrtf(var[l * D + c] + BN_EPS) * gamma[l * D + c];
    g_W1p[(l * D + k) * D + c] = W1[(l * D + k) * D + c] * s;
    if (k == 0)
        g_b1p[l * D + c] = (b1[l * D + c] - mean[l * D + c]) * s + beta[l * D + c];
}

// ---------------- CSR build --------------------------------------------------
__global__ void zero_deg(int* deg, int n) {
    int i = blockIdx.x * 256 + threadIdx.x;
    if (i < n) deg[i] = 0;
}

__global__ void hist_kernel(const int* __restrict__ ei, int* deg, int nE) {
    int e = blockIdx.x * 256 + threadIdx.x;
    if (e < nE) atomicAdd(&deg[__ldg(ei + nE + e)], 1);
}

// block-wise exclusive scan (512 elems/block)
__global__ void scan1(const int* __restrict__ deg, int* off, int* bsums, int n) {
    __shared__ int warpsum[16];
    int t = threadIdx.x;
    int i = blockIdx.x * 512 + t;
    int v = (i < n) ? deg[i] : 0;
    int lane = t & 31, w = t >> 5;
    int s = v;
#pragma unroll
    for (int o = 1; o < 32; o <<= 1) {
        int u = __shfl_up_sync(0xffffffffu, s, o);
        if (lane >= o) s += u;
    }
    if (lane == 31) warpsum[w] = s;
    __syncthreads();
    if (w == 0) {
        int ws = (lane < 16) ? warpsum[lane] : 0;
#pragma unroll
        for (int o = 1; o < 16; o <<= 1) {
            int u = __shfl_up_sync(0xffffffffu, ws, o);
            if (lane >= o) ws += u;
        }
        if (lane < 16) warpsum[lane] = ws;
    }
    __syncthreads();
    int base = (w > 0) ? warpsum[w - 1] : 0;
    if (i < n) off[i] = base + s - v;
    if (t == 0) bsums[blockIdx.x] = warpsum[15];
}

// exclusive scan of block sums (nb <= 256), one block of 256
__global__ void scan2(int* bsums, int nb) {
    __shared__ int ws[8];
    int t = threadIdx.x, lane = t & 31, w = t >> 5;
    int v = (t < nb) ? bsums[t] : 0;
    int s = v;
#pragma unroll
    for (int o = 1; o < 32; o <<= 1) {
        int u = __shfl_up_sync(0xffffffffu, s, o);
        if (lane >= o) s += u;
    }
    if (lane == 31) ws[w] = s;
    __syncthreads();
    if (w == 0 && lane < 8) {
        int a = ws[lane];
#pragma unroll
        for (int o = 1; o < 8; o <<= 1) {
            int u = __shfl_up_sync(0xffu, a, o);
            if (lane >= o) a += u;
        }
        ws[lane] = a;
    }
    __syncthreads();
    int base = (w > 0) ? ws[w - 1] : 0;
    if (t < nb) bsums[t] = base + s - v;
}

__global__ void scan3(int* off, const int* __restrict__ bsums, int* cur, int n, int nE) {
    int i = blockIdx.x * 256 + threadIdx.x;
    if (i < n) {
        int v = off[i] + bsums[i >> 9];
        off[i] = v;
        cur[i] = v;
    }
    if (i == 0) off[n] = nE;
}

__global__ void fill_csr(const int* __restrict__ ei, int* cur, int* col, int nE) {
    int e = blockIdx.x * 256 + threadIdx.x;
    if (e >= nE) return;
    int s = __ldg(ei + e);
    int d = __ldg(ei + nE + e);
    int p = atomicAdd(&cur[d], 1);
    col[p] = s;
}

// ---------------- aggregation: agg[i] = x[i] + sum_{j in N(i)} x[j] ---------
// warp per node; lane holds float4 (full 128-f row across the warp)
__global__ void gather_agg(const float* __restrict__ x,
                           const int* __restrict__ off,
                           const int* __restrict__ col,
                           float* __restrict__ agg, int n) {
    int node = blockIdx.x * 8 + (threadIdx.x >> 5);
    if (node >= n) return;
    int lane = threadIdx.x & 31;
    int beg = __ldg(off + node), end = __ldg(off + node + 1);
    float4 acc = __ldg((const float4*)x + (long long)node * 32 + lane);
    int e = beg;
    for (; e + 1 < end; e += 2) {
        int s0 = __ldg(col + e);
        int s1 = __ldg(col + e + 1);
        float4 v0 = __ldg((const float4*)x + (long long)s0 * 32 + lane);
        float4 v1 = __ldg((const float4*)x + (long long)s1 * 32 + lane);
        acc.x += v0.x; acc.y += v0.y; acc.z += v0.z; acc.w += v0.w;
        acc.x += v1.x; acc.y += v1.y; acc.z += v1.z; acc.w += v1.w;
    }
    if (e < end) {
        int s0 = __ldg(col + e);
        float4 v0 = __ldg((const float4*)x + (long long)s0 * 32 + lane);
        acc.x += v0.x; acc.y += v0.y; acc.z += v0.z; acc.w += v0.w;
    }
    ((float4*)agg)[(long long)node * 32 + lane] = acc;
}

// ---------------- pooling: g[batch[i]] += x[i] ------------------------------
__global__ void zero_kernel(float4* __restrict__ p, int n4) {
    int i = blockIdx.x * blockDim.x + threadIdx.x;
    if (i < n4) p[i] = make_float4(0.f, 0.f, 0.f, 0.f);
}

__global__ void pool_nodes(const float* __restrict__ x,
                           const int* __restrict__ batch,
                           float* __restrict__ g, int n) {
    int i = blockIdx.x * 8 + (threadIdx.x >> 5);
    if (i >= n) return;
    int lane = threadIdx.x & 31;
    int b = __ldg(batch + i);
    float4 v = __ldg((const float4*)x + (long long)i * 32 + lane);
    const float4* dp = (const float4*)g + (long long)b * 32 + lane;
    asm volatile("red.global.add.v4.f32 [%0], {%1, %2, %3, %4};"
                 :: "l"(dp), "f"(v.x), "f"(v.y), "f"(v.z), "f"(v.w)
                 : "memory");
}

// ---------------- GEMM: C[n,128] = act(A[n,128] @ W[128,128] + bias) --------
// BM=256 rows/block, 256 threads, per-thread 16 rows x 8 cols (f32x2 packed).
// K chunk = 16. smem traffic 1.5 B/lane-FFMA2 -> fma-pipe bound.
__global__ __launch_bounds__(256, 1) void gemm_kernel(
    const float* __restrict__ A, const float* __restrict__ W,
    const float* __restrict__ bias, float* __restrict__ C, int n, int relu) {
    __shared__ float4 As4[4][258];   // [k4][row], pad 2
    __shared__ float4 Ws4[16][32];   // [k][c4]

    int t = threadIdx.x;
    int tx = t & 15;                 // cols 4*tx..+3 and 64+4*tx..+3
    int ty = t >> 4;                 // rows 16*ty..+15
    int row0 = blockIdx.x * 256;

    unsigned long long acc[16][4];
#pragma unroll
    for (int i = 0; i < 16; i++)
#pragma unroll
        for (int j = 0; j < 4; j++) acc[i][j] = 0ull;

    for (int ko = 0; ko < 8; ko++) {
        // stage A tile (256 rows x 16 k) transposed: 1024 float4
#pragma unroll
        for (int it = 0; it < 4; it++) {
            int idx = it * 256 + t;
            int k4 = idx & 3;
            int row = idx >> 2;
            int gr = row0 + row;
            float4 v = make_float4(0.f, 0.f, 0.f, 0.f);
            if (gr < n) v = __ldg((const float4*)A + (long long)gr * 32 + ko * 4 + k4);
            As4[k4][row] = v;
        }
        // stage W chunk (16 k x 128 c): 512 float4
#pragma unroll
        for (int it = 0; it < 2; it++) {
            int idx = it * 256 + t;
            int kr = idx >> 5;
            int c4 = idx & 31;
            Ws4[kr][c4] = __ldg((const float4*)W + (long long)(ko * 16 + kr) * 32 + c4);
        }
        __syncthreads();

#pragma unroll
        for (int k4 = 0; k4 < 4; k4++) {
            unsigned long long w2[4][4];
#pragma unroll
            for (int kk = 0; kk < 4; kk++) {
                float4 wlo = Ws4[k4 * 4 + kk][tx];
                float4 whi = Ws4[k4 * 4 + kk][16 + tx];
                w2[kk][0] = pack2f(wlo.x, wlo.y);
                w2[kk][1] = pack2f(wlo.z, wlo.w);
                w2[kk][2] = pack2f(whi.x, whi.y);
                w2[kk][3] = pack2f(whi.z, whi.w);
            }
#pragma unroll
            for (int i = 0; i < 16; i++) {
                float4 a4 = As4[k4][ty * 16 + i];
#pragma unroll
                for (int kk = 0; kk < 4; kk++) {
                    float av = (kk == 0) ? a4.x : (kk == 1) ? a4.y : (kk == 2) ? a4.z : a4.w;
                    unsigned long long aa = pack_dup(av);
                    acc[i][0] = ffma2(aa, w2[kk][0], acc[i][0]);
                    acc[i][1] = ffma2(aa, w2[kk][1], acc[i][1]);
                    acc[i][2] = ffma2(aa, w2[kk][2], acc[i][2]);
                    acc[i][3] = ffma2(aa, w2[kk][3], acc[i][3]);
                }
            }
        }
        __syncthreads();
    }

    // epilogue
    float4 blo = __ldg((const float4*)bias + tx);
    float4 bhi = __ldg((const float4*)bias + 16 + tx);
#pragma unroll
    for (int i = 0; i < 16; i++) {
        int gr = row0 + ty * 16 + i;
        if (gr >= n) continue;
        float2 c0 = unpack2(acc[i][0]);
        float2 c1 = unpack2(acc[i][1]);
        float2 c2 = unpack2(acc[i][2]);
        float2 c3 = unpack2(acc[i][3]);
        float4 olo = make_float4(c0.x + blo.x, c0.y + blo.y, c1.x + blo.z, c1.y + blo.w);
        float4 ohi = make_float4(c2.x + bhi.x, c2.y + bhi.y, c3.x + bhi.z, c3.y + bhi.w);
        if (relu) {
            olo.x = fmaxf(olo.x, 0.f); olo.y = fmaxf(olo.y, 0.f);
            olo.z = fmaxf(olo.z, 0.f); olo.w = fmaxf(olo.w, 0.f);
            ohi.x = fmaxf(ohi.x, 0.f); ohi.y = fmaxf(ohi.y, 0.f);
            ohi.z = fmaxf(ohi.z, 0.f); ohi.w = fmaxf(ohi.w, 0.f);
        }
        ((float4*)C)[(long long)gr * 32 + tx] = olo;
        ((float4*)C)[(long long)gr * 32 + 16 + tx] = ohi;
    }
}

// ---------------- launch -----------------------------------------------------
extern "C" void kernel_launch(void* const* d_in, const int* in_sizes, int n_in,
                              void* d_out, int out_size) {
    const float* x        = (const float*)d_in[0];
    const int*   ei       = (const int*)d_in[1];      // int32 (JAX x64 disabled)
    const int*   batch    = (const int*)d_in[2];      // int32
    const float* W1       = (const float*)d_in[3];
    const float* b1       = (const float*)d_in[4];
    const float* gamma    = (const float*)d_in[5];
    const float* beta     = (const float*)d_in[6];
    const float* mean     = (const float*)d_in[7];
    const float* var      = (const float*)d_in[8];
    const float* W2       = (const float*)d_in[9];
    const float* b2       = (const float*)d_in[10];
    const float* hW1      = (const float*)d_in[11];
    const float* hb1      = (const float*)d_in[12];
    const float* hW2      = (const float*)d_in[13];
    const float* hb2      = (const float*)d_in[14];

    int n  = in_sizes[0] / D;
    int nE = in_sizes[1] / 2;

    float *agg, *h1, *xa, *xb, *W1p, *b1p, *pool, *hid;
    int *deg, *off, *cur, *col, *bsums;
    cudaGetSymbolAddress((void**)&agg,  g_agg);
    cudaGetSymbolAddress((void**)&h1,   g_h1);
    cudaGetSymbolAddress((void**)&xa,   g_xa);
    cudaGetSymbolAddress((void**)&xb,   g_xb);
    cudaGetSymbolAddress((void**)&W1p,  g_W1p);
    cudaGetSymbolAddress((void**)&b1p,  g_b1p);
    cudaGetSymbolAddress((void**)&pool, g_pool);
    cudaGetSymbolAddress((void**)&hid,  g_hid);
    cudaGetSymbolAddress((void**)&deg,  g_deg);
    cudaGetSymbolAddress((void**)&off,  g_off);
    cudaGetSymbolAddress((void**)&cur,  g_cur);
    cudaGetSymbolAddress((void**)&col,  g_col);
    cudaGetSymbolAddress((void**)&bsums, g_bsums);

    int gemmGrid = (n + 255) / 256;
    int nb = (n + 511) / 512;

    // BN fold + CSR build (CSR reused by all 3 layers)
    fold_bn_kernel<<<dim3(D, 3), D>>>(W1, b1, gamma, beta, mean, var);
    zero_deg<<<(n + 255) / 256, 256>>>(deg, n);
    hist_kernel<<<(nE + 255) / 256, 256>>>(ei, deg, nE);
    scan1<<<nb, 512>>>(deg, off, bsums, n);
    scan2<<<1, 256>>>(bsums, nb);
    scan3<<<(n + 255) / 256, 256>>>(off, bsums, cur, n, nE);
    fill_csr<<<(nE + 255) / 256, 256>>>(ei, cur, col, nE);

    const float* xin = x;
    float* outs[3] = {xa, xb, xa};
    for (int l = 0; l < 3; l++) {
        gather_agg<<<(n + 7) / 8, 256>>>(xin, off, col, agg, n);
        gemm_kernel<<<gemmGrid, 256>>>(agg, W1p + l * D * D, b1p + l * D, h1, n, 1);
        gemm_kernel<<<gemmGrid, 256>>>(h1, W2 + (long long)l * D * D, b2 + l * D, outs[l], n, 1);
        xin = outs[l];
    }

    zero_kernel<<<(NG * 32 + 255) / 256, 256>>>((float4*)pool, NG * 32);
    pool_nodes<<<(n + 7) / 8, 256>>>(xin, batch, pool, n);
    gemm_kernel<<<(NG + 255) / 256, 256>>>(pool, hW1, hb1, hid, NG, 1);
    gemm_kernel<<<(NG + 255) / 256, 256>>>(hid, hW2, hb2, (float*)d_out, NG, 0);
}

// round 9
// speedup vs baseline: 2.2251x; 1.6356x over previous
#include <cuda_runtime.h>
#include <cuda_bf16.h>
#include <cstdint>

#define D 128
#define NG 1024
#define MAXN 100000
#define MAXE 1600000
#define BN_EPS 1e-5f

// ---------------- scratch (static device memory) ----------------------------
__device__ float g_agg[MAXN * D];
__device__ float g_h1[MAXN * D];
__device__ float g_xa[MAXN * D];
__device__ float g_xb[MAXN * D];
__device__ float g_W1p[3 * D * D];
__device__ float g_b1p[3 * D];
__device__ float g_pool[NG * D];
__device__ float g_hid[NG * D];
// CSR
__device__ int g_deg[MAXN];
__device__ int g_off[MAXN + 1];
__device__ int g_cur[MAXN];
__device__ int g_col[MAXE];
__device__ int g_bsums[256];
// pre-split weights, plain [n][k] layout (col-major B for mma .row.col):
// mats: 0..2 = BN-folded W1, 3..5 = W2, 6 = head W1, 7 = head W2
__device__ __nv_bfloat16 g_Wt_hi[8 * D * D];
__device__ __nv_bfloat16 g_Wt_lo[8 * D * D];

// ---------------- helpers ----------------------------------------------------
__device__ __forceinline__ uint32_t smem_u32(const void* p) {
    uint32_t a;
    asm("{ .reg .u64 t; cvta.to.shared.u64 t, %1; cvt.u32.u64 %0, t; }"
        : "=r"(a) : "l"(p));
    return a;
}

__device__ __forceinline__ void mma16816(float& c0, float& c1, float& c2, float& c3,
                                         uint32_t a0, uint32_t a1, uint32_t a2, uint32_t a3,
                                         uint32_t b0, uint32_t b1) {
    asm volatile("mma.sync.aligned.m16n8k16.row.col.f32.bf16.bf16.f32 "
                 "{%0,%1,%2,%3}, {%4,%5,%6,%7}, {%8,%9}, {%0,%1,%2,%3};"
                 : "+f"(c0), "+f"(c1), "+f"(c2), "+f"(c3)
                 : "r"(a0), "r"(a1), "r"(a2), "r"(a3), "r"(b0), "r"(b1));
}

// ---------------- fold BN into W1/b1 ----------------------------------------
__global__ void fold_bn_kernel(const float* __restrict__ W1,
                               const float* __restrict__ b1,
                               const float* __restrict__ gamma,
                               const float* __restrict__ beta,
                               const float* __restrict__ mean,
                               const float* __restrict__ var) {
    int k = blockIdx.x;
    int l = blockIdx.y;
    int c = threadIdx.x;
    float s = rsqrtf(var[l * D + c] + BN_EPS) * gamma[l * D + c];
    g_W1p[(l * D + k) * D + c] = W1[(l * D + k) * D + c] * s;
    if (k == 0)
        g_b1p[l * D + c] = (b1[l * D + c] - mean[l * D + c]) * s + beta[l * D + c];
}

// ---------------- pre-split weights: Wt[n][k] = W[k][n], hi/lo bf16 ----------
__global__ void prep_w_kernel(const float* __restrict__ W2,
                              const float* __restrict__ hW1,
                              const float* __restrict__ hW2) {
    int idx = blockIdx.x * 256 + threadIdx.x;   // 0..16383
    int m = blockIdx.y;                          // 0..7
    int nn = idx & 127;
    int k  = idx >> 7;
    float w;
    if (m < 3)      w = g_W1p[m * D * D + k * D + nn];
    else if (m < 6) w = W2[(m - 3) * D * D + k * D + nn];
    else if (m == 6) w = hW1[k * D + nn];
    else             w = hW2[k * D + nn];
    __nv_bfloat16 hi = __float2bfloat16(w);
    float rem = w - __bfloat162float(hi);
    __nv_bfloat16 lo = __float2bfloat16(rem);
    int off = m * D * D + nn * D + k;           // [mat][n][k]
    g_Wt_hi[off] = hi;
    g_Wt_lo[off] = lo;
}

// ---------------- CSR build --------------------------------------------------
__global__ void zero_deg(int* deg, int n) {
    int i = blockIdx.x * 256 + threadIdx.x;
    if (i < n) deg[i] = 0;
}

__global__ void hist_kernel(const int* __restrict__ ei, int* deg, int nE) {
    int e = blockIdx.x * 256 + threadIdx.x;
    if (e < nE) atomicAdd(&deg[__ldg(ei + nE + e)], 1);
}

__global__ void scan1(const int* __restrict__ deg, int* off, int* bsums, int n) {
    __shared__ int warpsum[16];
    int t = threadIdx.x;
    int i = blockIdx.x * 512 + t;
    int v = (i < n) ? deg[i] : 0;
    int lane = t & 31, w = t >> 5;
    int s = v;
#pragma unroll
    for (int o = 1; o < 32; o <<= 1) {
        int u = __shfl_up_sync(0xffffffffu, s, o);
        if (lane >= o) s += u;
    }
    if (lane == 31) warpsum[w] = s;
    __syncthreads();
    if (w == 0) {
        int ws = (lane < 16) ? warpsum[lane] : 0;
#pragma unroll
        for (int o = 1; o < 16; o <<= 1) {
            int u = __shfl_up_sync(0xffffffffu, ws, o);
            if (lane >= o) ws += u;
        }
        if (lane < 16) warpsum[lane] = ws;
    }
    __syncthreads();
    int base = (w > 0) ? warpsum[w - 1] : 0;
    if (i < n) off[i] = base + s - v;
    if (t == 0) bsums[blockIdx.x] = warpsum[15];
}

__global__ void scan2(int* bsums, int nb) {
    __shared__ int ws[8];
    int t = threadIdx.x, lane = t & 31, w = t >> 5;
    int v = (t < nb) ? bsums[t] : 0;
    int s = v;
#pragma unroll
    for (int o = 1; o < 32; o <<= 1) {
        int u = __shfl_up_sync(0xffffffffu, s, o);
        if (lane >= o) s += u;
    }
    if (lane == 31) ws[w] = s;
    __syncthreads();
    if (w == 0 && lane < 8) {
        int a = ws[lane];
#pragma unroll
        for (int o = 1; o < 8; o <<= 1) {
            int u = __shfl_up_sync(0xffu, a, o);
            if (lane >= o) a += u;
        }
        ws[lane] = a;
    }
    __syncthreads();
    int base = (w > 0) ? ws[w - 1] : 0;
    if (t < nb) bsums[t] = base + s - v;
}

__global__ void scan3(int* off, const int* __restrict__ bsums, int* cur, int n, int nE) {
    int i = blockIdx.x * 256 + threadIdx.x;
    if (i < n) {
        int v = off[i] + bsums[i >> 9];
        off[i] = v;
        cur[i] = v;
    }
    if (i == 0) off[n] = nE;
}

__global__ void fill_csr(const int* __restrict__ ei, int* cur, int* col, int nE) {
    int e = blockIdx.x * 256 + threadIdx.x;
    if (e >= nE) return;
    int s = __ldg(ei + e);
    int d = __ldg(ei + nE + e);
    int p = atomicAdd(&cur[d], 1);
    col[p] = s;
}

// ---------------- aggregation: agg[i] = x[i] + sum_{j in N(i)} x[j] ---------
__global__ void gather_agg(const float* __restrict__ x,
                           const int* __restrict__ off,
                           const int* __restrict__ col,
                           float* __restrict__ agg, int n) {
    int node = blockIdx.x * 8 + (threadIdx.x >> 5);
    if (node >= n) return;
    int lane = threadIdx.x & 31;
    int beg = __ldg(off + node), end = __ldg(off + node + 1);
    float4 acc = __ldg((const float4*)x + (long long)node * 32 + lane);
    int e = beg;
    for (; e + 1 < end; e += 2) {
        int s0 = __ldg(col + e);
        int s1 = __ldg(col + e + 1);
        float4 v0 = __ldg((const float4*)x + (long long)s0 * 32 + lane);
        float4 v1 = __ldg((const float4*)x + (long long)s1 * 32 + lane);
        acc.x += v0.x; acc.y += v0.y; acc.z += v0.z; acc.w += v0.w;
        acc.x += v1.x; acc.y += v1.y; acc.z += v1.z; acc.w += v1.w;
    }
    if (e < end) {
        int s0 = __ldg(col + e);
        float4 v0 = __ldg((const float4*)x + (long long)s0 * 32 + lane);
        acc.x += v0.x; acc.y += v0.y; acc.z += v0.z; acc.w += v0.w;
    }
    ((float4*)agg)[(long long)node * 32 + lane] = acc;
}

// ---------------- pooling ----------------------------------------------------
__global__ void zero_kernel(float4* __restrict__ p, int n4) {
    int i = blockIdx.x * blockDim.x + threadIdx.x;
    if (i < n4) p[i] = make_float4(0.f, 0.f, 0.f, 0.f);
}

__global__ void pool_nodes(const float* __restrict__ x,
                           const int* __restrict__ batch,
                           float* __restrict__ g, int n) {
    int i = blockIdx.x * 8 + (threadIdx.x >> 5);
    if (i >= n) return;
    int lane = threadIdx.x & 31;
    int b = __ldg(batch + i);
    float4 v = __ldg((const float4*)x + (long long)i * 32 + lane);
    const float4* dp = (const float4*)g + (long long)b * 32 + lane;
    asm volatile("red.global.add.v4.f32 [%0], {%1, %2, %3, %4};"
                 :: "l"(dp), "f"(v.x), "f"(v.y), "f"(v.z), "f"(v.w)
                 : "memory");
}

// ---------------- mma.sync GEMM: C[n,128] = act(A @ W_mat + bias) -----------
// 128 rows x 128 cols per block, 256 threads = 8 warps (16 rows each).
// 3-term bf16 split: Ahi*Bhi + Ahi*Blo + Alo*Bhi, fp32 accumulators.
// smem tiles: pitch 136 bf16 (272B) -> ldmatrix 8-row phases hit 32 distinct banks.
#define PITCH 136
#define TILE_B (128 * PITCH * 2)          // 34816 bytes per tile
#define SA_HI 0
#define SA_LO TILE_B
#define SB_HI (2 * TILE_B)
#define SB_LO (3 * TILE_B)
#define S_BIAS (4 * TILE_B)
#define GEMM_SMEM (4 * TILE_B + 512)

__global__ __launch_bounds__(256, 1) void gemm_tc(
    const float* __restrict__ A, int mat,
    const float* __restrict__ bias, float* __restrict__ C, int n, int relu) {
    extern __shared__ char smp[];
    uint32_t base = smem_u32(smp);

    int t = threadIdx.x;
    int wid = t >> 5;
    int lane = t & 31;
    int row0 = blockIdx.x * 128;

    // ---- stage A: load f32, split hi/lo bf16 ----
#pragma unroll
    for (int it = 0; it < 16; it++) {
        int idx = it * 256 + t;        // 0..4095 float4 slots
        int row = idx >> 5;
        int k4 = idx & 31;             // k = k4*4
        float4 v = make_float4(0.f, 0.f, 0.f, 0.f);
        if (row0 + row < n) v = __ldg((const float4*)A + (long long)(row0 + row) * 32 + k4);
        __nv_bfloat16 h0 = __float2bfloat16(v.x), h1 = __float2bfloat16(v.y);
        __nv_bfloat16 h2 = __float2bfloat16(v.z), h3 = __float2bfloat16(v.w);
        __nv_bfloat16 l0 = __float2bfloat16(v.x - __bfloat162float(h0));
        __nv_bfloat16 l1 = __float2bfloat16(v.y - __bfloat162float(h1));
        __nv_bfloat16 l2 = __float2bfloat16(v.z - __bfloat162float(h2));
        __nv_bfloat16 l3 = __float2bfloat16(v.w - __bfloat162float(h3));
        uint2 hp, lp;
        hp.x = ((uint32_t)__bfloat16_as_ushort(h1) << 16) | __bfloat16_as_ushort(h0);
        hp.y = ((uint32_t)__bfloat16_as_ushort(h3) << 16) | __bfloat16_as_ushort(h2);
        lp.x = ((uint32_t)__bfloat16_as_ushort(l1) << 16) | __bfloat16_as_ushort(l0);
        lp.y = ((uint32_t)__bfloat16_as_ushort(l3) << 16) | __bfloat16_as_ushort(l2);
        int off = row * (PITCH * 2) + k4 * 8;
        *(uint2*)(smp + SA_HI + off) = hp;
        *(uint2*)(smp + SA_LO + off) = lp;
    }
    // ---- stage B: copy preformatted [n][k] tiles with pitch padding ----
    {
        const float4* bh = (const float4*)g_Wt_hi + (size_t)mat * 2048;
        const float4* bl = (const float4*)g_Wt_lo + (size_t)mat * 2048;
#pragma unroll
        for (int it = 0; it < 8; it++) {
            int idx = it * 256 + t;        // 0..2047: nn = idx>>4, c16 = idx&15
            int nn = idx >> 4;
            int c16 = idx & 15;
            int off = nn * (PITCH * 2) + c16 * 16;
            *(float4*)(smp + SB_HI + off) = __ldg(bh + idx);
            *(float4*)(smp + SB_LO + off) = __ldg(bl + idx);
        }
    }
    if (t < 32) ((float4*)(smp + S_BIAS))[t] = __ldg((const float4*)bias + t);
    __syncthreads();

    // ---- main loop ----
    int m0 = wid * 16;
    float acc[16][4];
#pragma unroll
    for (int i = 0; i < 16; i++)
#pragma unroll
        for (int j = 0; j < 4; j++) acc[i][j] = 0.f;

    // A ldmatrix address pattern (x4): mat = lane>>3, r = lane&7
    int amat = lane >> 3;
    int arow = m0 + (lane & 7) + ((amat & 1) << 3);
    int akof = (amat >> 1) << 3;
    // B ldmatrix address pattern (x2): lanes 0-15 used
    int l16 = lane & 15;
    int bn = l16 & 7;
    int bkof = (l16 >> 3) << 3;

#pragma unroll
    for (int k16 = 0; k16 < 8; k16++) {
        int kb = k16 * 16;
        uint32_t ah0, ah1, ah2, ah3, al0, al1, al2, al3;
        uint32_t aaddr = base + SA_HI + arow * (PITCH * 2) + (kb + akof) * 2;
        asm volatile("ldmatrix.sync.aligned.m8n8.x4.shared.b16 {%0,%1,%2,%3}, [%4];"
                     : "=r"(ah0), "=r"(ah1), "=r"(ah2), "=r"(ah3) : "r"(aaddr));
        asm volatile("ldmatrix.sync.aligned.m8n8.x4.shared.b16 {%0,%1,%2,%3}, [%4];"
                     : "=r"(al0), "=r"(al1), "=r"(al2), "=r"(al3)
                     : "r"(aaddr + (uint32_t)(SA_LO - SA_HI)));
#pragma unroll
        for (int nt = 0; nt < 16; nt++) {
            uint32_t bh0, bh1, bl0, bl1;
            uint32_t baddr = base + SB_HI + (nt * 8 + bn) * (PITCH * 2) + (kb + bkof) * 2;
            asm volatile("ldmatrix.sync.aligned.m8n8.x2.shared.b16 {%0,%1}, [%2];"
                         : "=r"(bh0), "=r"(bh1) : "r"(baddr));
            asm volatile("ldmatrix.sync.aligned.m8n8.x2.shared.b16 {%0,%1}, [%2];"
                         : "=r"(bl0), "=r"(bl1) : "r"(baddr + (uint32_t)(SB_LO - SB_HI)));
            mma16816(acc[nt][0], acc[nt][1], acc[nt][2], acc[nt][3],
                     ah0, ah1, ah2, ah3, bh0, bh1);
            mma16816(acc[nt][0], acc[nt][1], acc[nt][2], acc[nt][3],
                     ah0, ah1, ah2, ah3, bl0, bl1);
            mma16816(acc[nt][0], acc[nt][1], acc[nt][2], acc[nt][3],
                     al0, al1, al2, al3, bh0, bh1);
        }
    }

    // ---- epilogue: C frag thread t holds rows (t/4, t/4+8), cols 2*(t%4)(+1)
    const float* bias_s = (const float*)(smp + S_BIAS);
    int r0 = row0 + m0 + (lane >> 2);
    int cq = (lane & 3) * 2;
#pragma unroll
    for (int nt = 0; nt < 16; nt++) {
        int col = nt * 8 + cq;
        float b0 = bias_s[col], b1 = bias_s[col + 1];
        float2 v0 = make_float2(acc[nt][0] + b0, acc[nt][1] + b1);
        float2 v1 = make_float2(acc[nt][2] + b0, acc[nt][3] + b1);
        if (relu) {
            v0.x = fmaxf(v0.x, 0.f); v0.y = fmaxf(v0.y, 0.f);
            v1.x = fmaxf(v1.x, 0.f); v1.y = fmaxf(v1.y, 0.f);
        }
        if (r0 < n)     *(float2*)(C + (long long)r0 * D + col) = v0;
        if (r0 + 8 < n) *(float2*)(C + (long long)(r0 + 8) * D + col) = v1;
    }
}

// ---------------- launch -----------------------------------------------------
extern "C" void kernel_launch(void* const* d_in, const int* in_sizes, int n_in,
                              void* d_out, int out_size) {
    const float* x        = (const float*)d_in[0];
    const int*   ei       = (const int*)d_in[1];      // int32 (JAX x64 disabled)
    const int*   batch    = (const int*)d_in[2];      // int32
    const float* W1       = (const float*)d_in[3];
    const float* b1       = (const float*)d_in[4];
    const float* gamma    = (const float*)d_in[5];
    const float* beta     = (const float*)d_in[6];
    const float* mean     = (const float*)d_in[7];
    const float* var      = (const float*)d_in[8];
    const float* W2       = (const float*)d_in[9];
    const float* b2       = (const float*)d_in[10];
    const float* hW1      = (const float*)d_in[11];
    const float* hb1      = (const float*)d_in[12];
    const float* hW2      = (const float*)d_in[13];
    const float* hb2      = (const float*)d_in[14];

    int n  = in_sizes[0] / D;
    int nE = in_sizes[1] / 2;

    float *agg, *h1, *xa, *xb, *b1p, *pool, *hid;
    int *deg, *off, *cur, *col, *bsums;
    cudaGetSymbolAddress((void**)&agg,  g_agg);
    cudaGetSymbolAddress((void**)&h1,   g_h1);
    cudaGetSymbolAddress((void**)&xa,   g_xa);
    cudaGetSymbolAddress((void**)&xb,   g_xb);
    cudaGetSymbolAddress((void**)&b1p,  g_b1p);
    cudaGetSymbolAddress((void**)&pool, g_pool);
    cudaGetSymbolAddress((void**)&hid,  g_hid);
    cudaGetSymbolAddress((void**)&deg,  g_deg);
    cudaGetSymbolAddress((void**)&off,  g_off);
    cudaGetSymbolAddress((void**)&cur,  g_cur);
    cudaGetSymbolAddress((void**)&col,  g_col);
    cudaGetSymbolAddress((void**)&bsums, g_bsums);

    cudaFuncSetAttribute(gemm_tc, cudaFuncAttributeMaxDynamicSharedMemorySize, GEMM_SMEM);

    int gemmGrid = (n + 127) / 128;
    int nb = (n + 511) / 512;

    // prep: BN fold, weight split, CSR build
    fold_bn_kernel<<<dim3(D, 3), D>>>(W1, b1, gamma, beta, mean, var);
    prep_w_kernel<<<dim3(64, 8), 256>>>(W2, hW1, hW2);
    zero_deg<<<(n + 255) / 256, 256>>>(deg, n);
    hist_kernel<<<(nE + 255) / 256, 256>>>(ei, deg, nE);
    scan1<<<nb, 512>>>(deg, off, bsums, n);
    scan2<<<1, 256>>>(bsums, nb);
    scan3<<<(n + 255) / 256, 256>>>(off, bsums, cur, n, nE);
    fill_csr<<<(nE + 255) / 256, 256>>>(ei, cur, col, nE);

    const float* xin = x;
    float* outs[3] = {xa, xb, xa};
    for (int l = 0; l < 3; l++) {
        gather_agg<<<(n + 7) / 8, 256>>>(xin, off, col, agg, n);
        gemm_tc<<<gemmGrid, 256, GEMM_SMEM>>>(agg, l, b1p + l * D, h1, n, 1);
        gemm_tc<<<gemmGrid, 256, GEMM_SMEM>>>(h1, 3 + l, b2 + l * D, outs[l], n, 1);
        xin = outs[l];
    }

    zero_kernel<<<(NG * 32 + 255) / 256, 256>>>((float4*)pool, NG * 32);
    pool_nodes<<<(n + 7) / 8, 256>>>(xin, batch, pool, n);
    gemm_tc<<<NG / 128, 256, GEMM_SMEM>>>(pool, 6, hb1, hid, NG, 1);
    gemm_tc<<<NG / 128, 256, GEMM_SMEM>>>(hid, 7, hb2, (float*)d_out, NG, 0);
}